// round 4
// baseline (speedup 1.0000x reference)
#include <cuda_runtime.h>

// GraphNorm: x (131072, 256) fp32, 64 graphs x 2048 rows x 256 units.
// out = gamma * (x - mean_g,u) / (std_g,u + 1e-5) + beta.
//
// MLP-focused 3-kernel pipeline:
//   k1: partial stats, 16 v8 loads/thread in explicit batches of 4
//       (32 value regs in flight) -> deep memory-level parallelism.
//   k2: finalize mean / inv(std+eps).
//   k3: streaming normalize, software-pipelined pairs of iterations:
//       6 v8 loads in flight (x, gamma, beta for 2 rows) before compute.
// x read with L2::evict_last in k1 (stays resident for k3's re-read),
// streaming operands evict_first, outputs st.global.cs.

#define UNITS   256
#define BATCH   64
#define NPG     2048
#define UB      32
#define VEC     8
#define EPS     1e-5f

#define S1      2           // k1 row slices (1024 rows each)
#define S3      4           // k3 row slices (512 rows each)
#define T256    256

__device__ float g_psum[S1][BATCH][UNITS];
__device__ float g_psq [S1][BATCH][UNITS];
__device__ float g_mean[BATCH][UNITS];
__device__ float g_inv [BATCH][UNITS];

__device__ __forceinline__ void ld_v8_evict_last(const float* p, float* r) {
    asm volatile("ld.global.L2::evict_last.v8.b32 {%0,%1,%2,%3,%4,%5,%6,%7}, [%8];"
                 : "=f"(r[0]), "=f"(r[1]), "=f"(r[2]), "=f"(r[3]),
                   "=f"(r[4]), "=f"(r[5]), "=f"(r[6]), "=f"(r[7])
                 : "l"(p));
}
__device__ __forceinline__ void ld_v8_evict_first(const float* p, float* r) {
    asm volatile("ld.global.L2::evict_first.v8.b32 {%0,%1,%2,%3,%4,%5,%6,%7}, [%8];"
                 : "=f"(r[0]), "=f"(r[1]), "=f"(r[2]), "=f"(r[3]),
                   "=f"(r[4]), "=f"(r[5]), "=f"(r[6]), "=f"(r[7])
                 : "l"(p));
}
__device__ __forceinline__ void st_v4_cs(float* p, float a, float b, float c, float d) {
    asm volatile("st.global.cs.v4.f32 [%0], {%1,%2,%3,%4};"
                 :: "l"(p), "f"(a), "f"(b), "f"(c), "f"(d));
}

// ---------------- k1: partial stats ----------------
// grid (8, 64, 2), 256 threads. Block: rows [z*1024, +1024) x units [uc*32, +32).
// Per thread: 16 rows (stride 64), loads issued in batches of 4.
__global__ void __launch_bounds__(T256, 4)
k1_partial_stats(const float* __restrict__ x)
{
    const int uc    = blockIdx.x;
    const int g     = blockIdx.y;
    const int slice = blockIdx.z;
    const int lane  = threadIdx.x & 31;
    const int w     = threadIdx.x >> 5;       // 0..7
    const int ug    = lane & 3;               // 8 units each
    const int rg    = lane >> 2;              // 0..7

    const float* px = x + (size_t)g * NPG * UNITS
                        + (size_t)(slice * 1024 + w * 8 + rg) * UNITS
                        + (size_t)uc * UB + (size_t)ug * VEC;
    const size_t rstride = (size_t)64 * UNITS;   // 64 rows between iterations

    float sum[VEC], sq[VEC];
    #pragma unroll
    for (int j = 0; j < VEC; ++j) { sum[j] = 0.f; sq[j] = 0.f; }

    #pragma unroll
    for (int b = 0; b < 4; ++b) {             // 4 batches x 4 loads = 16 rows
        float v[4][VEC];
        #pragma unroll
        for (int k = 0; k < 4; ++k)
            ld_v8_evict_last(px + (size_t)(b * 4 + k) * rstride, v[k]);
        #pragma unroll
        for (int k = 0; k < 4; ++k)
            #pragma unroll
            for (int j = 0; j < VEC; ++j) {
                sum[j] += v[k][j];
                sq[j] = fmaf(v[k][j], v[k][j], sq[j]);
            }
    }

    // reduce over the 8 row-subgroups within the warp (lane bits 2..4)
    #pragma unroll
    for (int m = 4; m <= 16; m <<= 1) {
        #pragma unroll
        for (int j = 0; j < VEC; ++j) {
            sum[j] += __shfl_xor_sync(0xffffffffu, sum[j], m);
            sq[j]  += __shfl_xor_sync(0xffffffffu, sq[j],  m);
        }
    }

    __shared__ float s_sum[8][UB];
    __shared__ float s_sq [8][UB];
    if (lane < 4) {
        #pragma unroll
        for (int j = 0; j < VEC; ++j) {
            s_sum[w][ug * VEC + j] = sum[j];
            s_sq [w][ug * VEC + j] = sq[j];
        }
    }
    __syncthreads();

    if (w == 0) {                             // 32 lanes <-> 32 units
        float a = 0.f, b = 0.f;
        #pragma unroll
        for (int k = 0; k < 8; ++k) {
            a += s_sum[k][lane];
            b += s_sq [k][lane];
        }
        const int u = uc * UB + lane;
        g_psum[slice][g][u] = a;
        g_psq [slice][g][u] = b;
    }
}

// ---------------- k2: finalize ----------------
__global__ void __launch_bounds__(T256)
k2_finalize()
{
    const int g = blockIdx.x;
    const int u = threadIdx.x;
    float s = 0.f, q = 0.f;
    #pragma unroll
    for (int k = 0; k < S1; ++k) {
        s += g_psum[k][g][u];
        q += g_psq [k][g][u];
    }
    const float invn = 1.0f / (float)NPG;
    const float mean = s * invn;
    float var = fmaf(-mean, mean, q * invn);
    var = fmaxf(var, 0.0f);
    g_mean[g][u] = mean;
    g_inv [g][u] = 1.0f / (sqrtf(var) + EPS);
}

// ---------------- k3: streaming normalize ----------------
// grid (8, 64, 4), 256 threads. Block: rows [z*512, +512) x units [uc*32, +32).
// 8 iterations per thread (stride 64 rows), processed in pipelined pairs:
// all 6 loads (x,g,b for two rows) issued before any compute.
__global__ void __launch_bounds__(T256, 3)
k3_normalize(const float* __restrict__ x,
             const float* __restrict__ gamma,
             const float* __restrict__ beta,
             float* __restrict__ out)
{
    const int uc    = blockIdx.x;
    const int g     = blockIdx.y;
    const int slice = blockIdx.z;
    const int lane  = threadIdx.x & 31;
    const int w     = threadIdx.x >> 5;
    const int ug    = lane & 3;
    const int rg    = lane >> 2;

    const size_t ubase = (size_t)uc * UB + (size_t)ug * VEC;
    const size_t off0  = (size_t)g * NPG * UNITS
                       + (size_t)(slice * 512 + w * 8 + rg) * UNITS + ubase;
    const size_t rstride = (size_t)64 * UNITS;

    float mean[VEC], inv[VEC];
    {
        const float4 m0 = *(const float4*)(&g_mean[g][0] + ubase);
        const float4 m1 = *(const float4*)(&g_mean[g][0] + ubase + 4);
        const float4 i0 = *(const float4*)(&g_inv [g][0] + ubase);
        const float4 i1 = *(const float4*)(&g_inv [g][0] + ubase + 4);
        mean[0]=m0.x; mean[1]=m0.y; mean[2]=m0.z; mean[3]=m0.w;
        mean[4]=m1.x; mean[5]=m1.y; mean[6]=m1.z; mean[7]=m1.w;
        inv[0]=i0.x; inv[1]=i0.y; inv[2]=i0.z; inv[3]=i0.w;
        inv[4]=i1.x; inv[5]=i1.y; inv[6]=i1.z; inv[7]=i1.w;
    }

    #pragma unroll
    for (int p = 0; p < 4; ++p) {             // 4 pairs = 8 rows
        const size_t idx0 = off0 + (size_t)(2 * p)     * rstride;
        const size_t idx1 = off0 + (size_t)(2 * p + 1) * rstride;
        float v0[VEC], ga0[VEC], be0[VEC];
        float v1[VEC], ga1[VEC], be1[VEC];
        ld_v8_evict_first(x     + idx0, v0);
        ld_v8_evict_first(gamma + idx0, ga0);
        ld_v8_evict_first(beta  + idx0, be0);
        ld_v8_evict_first(x     + idx1, v1);
        ld_v8_evict_first(gamma + idx1, ga1);
        ld_v8_evict_first(beta  + idx1, be1);

        float o0[VEC], o1[VEC];
        #pragma unroll
        for (int j = 0; j < VEC; ++j) {
            o0[j] = fmaf((v0[j] - mean[j]) * inv[j], ga0[j], be0[j]);
            o1[j] = fmaf((v1[j] - mean[j]) * inv[j], ga1[j], be1[j]);
        }
        st_v4_cs(out + idx0,     o0[0], o0[1], o0[2], o0[3]);
        st_v4_cs(out + idx0 + 4, o0[4], o0[5], o0[6], o0[7]);
        st_v4_cs(out + idx1,     o1[0], o1[1], o1[2], o1[3]);
        st_v4_cs(out + idx1 + 4, o1[4], o1[5], o1[6], o1[7]);
    }
}

extern "C" void kernel_launch(void* const* d_in, const int* in_sizes, int n_in,
                              void* d_out, int out_size) {
    const float* x     = (const float*)d_in[0];
    const float* gamma = (const float*)d_in[1];
    const float* beta  = (const float*)d_in[2];
    float* out = (float*)d_out;

    dim3 g1(UNITS / UB, BATCH, S1);   // (8, 64, 2)
    k1_partial_stats<<<g1, T256>>>(x);
    k2_finalize<<<BATCH, T256>>>();
    dim3 g3(UNITS / UB, BATCH, S3);   // (8, 64, 4)
    k3_normalize<<<g3, T256>>>(x, gamma, beta, out);
}

// round 5
// speedup vs baseline: 1.0439x; 1.0439x over previous
#include <cuda_runtime.h>

// GraphNorm: x (131072, 256) fp32, 64 graphs x 2048 rows x 256 units.
// out = gamma * (x - mean_g,u) / (std_g,u + 1e-5) + beta.
//
// Fused single kernel (preserves temporal L2 reuse of x between passes;
// split-kernel variants lose it since x ~= full L2).
// Block = (graph, 32-unit chunk), grid (8, 64), 1024 threads.
//  - pass1: batch-4 v8 evict_last loads (32 value regs in flight)
//  - pass2: pipelined row-pairs, 6 v8 evict_first loads in flight,
//           mean/inv read from smem float2 (frees registers),
//           single-base + immediate-offset addressing, st.global.cs.v4.

#define UNITS   256
#define BATCH   64
#define NPG     2048
#define UB      32
#define NWARPS  32
#define THREADS 1024
#define VEC     8
#define EPS     1e-5f
// row stride between successive per-thread iterations: 256 rows
#define RSTRIDE ((size_t)256 * UNITS)

__device__ __forceinline__ void ld_v8_evict_last(const float* p, float* r) {
    asm volatile("ld.global.L2::evict_last.v8.b32 {%0,%1,%2,%3,%4,%5,%6,%7}, [%8];"
                 : "=f"(r[0]), "=f"(r[1]), "=f"(r[2]), "=f"(r[3]),
                   "=f"(r[4]), "=f"(r[5]), "=f"(r[6]), "=f"(r[7])
                 : "l"(p));
}
__device__ __forceinline__ void ld_v8_evict_first(const float* p, float* r) {
    asm volatile("ld.global.L2::evict_first.v8.b32 {%0,%1,%2,%3,%4,%5,%6,%7}, [%8];"
                 : "=f"(r[0]), "=f"(r[1]), "=f"(r[2]), "=f"(r[3]),
                   "=f"(r[4]), "=f"(r[5]), "=f"(r[6]), "=f"(r[7])
                 : "l"(p));
}
__device__ __forceinline__ void st_v4_cs(float* p, float a, float b, float c, float d) {
    asm volatile("st.global.cs.v4.f32 [%0], {%1,%2,%3,%4};"
                 :: "l"(p), "f"(a), "f"(b), "f"(c), "f"(d));
}

__global__ void __launch_bounds__(THREADS)
graphnorm_kernel(const float* __restrict__ x,
                 const float* __restrict__ gamma,
                 const float* __restrict__ beta,
                 float* __restrict__ out)
{
    const int uc   = blockIdx.x;           // unit chunk 0..7
    const int g    = blockIdx.y;           // graph 0..63
    const int lane = threadIdx.x & 31;
    const int w    = threadIdx.x >> 5;     // warp 0..31
    const int ug   = lane & 3;             // 8-unit subgroup 0..3
    const int rg   = lane >> 2;            // row subgroup 0..7

    // per-thread base: graph g, row (w*8+rg), units uc*32 + ug*8
    const size_t base = (size_t)g * NPG * UNITS
                      + (size_t)(w * 8 + rg) * UNITS
                      + (size_t)uc * UB + (size_t)ug * VEC;
    const float* xb = x + base;

    // ---------------- pass 1: sum / sumsq (8 rows, batches of 4) ----------------
    float sum[VEC], sq[VEC];
    #pragma unroll
    for (int j = 0; j < VEC; ++j) { sum[j] = 0.f; sq[j] = 0.f; }

    #pragma unroll
    for (int b = 0; b < 2; ++b) {
        float v[4][VEC];
        #pragma unroll
        for (int k = 0; k < 4; ++k)
            ld_v8_evict_last(xb + (size_t)(b * 4 + k) * RSTRIDE, v[k]);
        #pragma unroll
        for (int k = 0; k < 4; ++k)
            #pragma unroll
            for (int j = 0; j < VEC; ++j) {
                sum[j] += v[k][j];
                sq[j] = fmaf(v[k][j], v[k][j], sq[j]);
            }
    }

    // warp reduce over 8 row-subgroups (lane bits 2..4)
    #pragma unroll
    for (int m = 4; m <= 16; m <<= 1) {
        #pragma unroll
        for (int j = 0; j < VEC; ++j) {
            sum[j] += __shfl_xor_sync(0xffffffffu, sum[j], m);
            sq[j]  += __shfl_xor_sync(0xffffffffu, sq[j],  m);
        }
    }

    __shared__ float s_sum[NWARPS][UB];
    __shared__ float s_sq [NWARPS][UB];
    if (lane < 4) {
        #pragma unroll
        for (int j = 0; j < VEC; ++j) {
            s_sum[w][ug * VEC + j] = sum[j];
            s_sq [w][ug * VEC + j] = sq[j];
        }
    }
    __syncthreads();

    #pragma unroll
    for (int stride = NWARPS / 2; stride > 0; stride >>= 1) {
        if (w < stride && lane < 4) {
            #pragma unroll
            for (int j = 0; j < VEC; ++j) {
                const int u = ug * VEC + j;
                s_sum[w][u] += s_sum[w + stride][u];
                s_sq [w][u] += s_sq [w + stride][u];
            }
        }
        __syncthreads();
    }

    __shared__ float2 s_mi[UB];           // {mean, inv} per unit in chunk
    if (w == 0) {
        const float invn = 1.0f / (float)NPG;
        const float mean = s_sum[0][lane] * invn;
        float var = fmaf(-mean, mean, s_sq[0][lane] * invn);
        var = fmaxf(var, 0.0f);
        s_mi[lane] = make_float2(mean, 1.0f / (sqrtf(var) + EPS));
    }
    __syncthreads();

    // ---------------- pass 2: normalize + affine (pipelined pairs) ----------------
    const float* gb = gamma + base;
    const float* bb = beta  + base;
    float*       ob = out   + base;

    #pragma unroll
    for (int p = 0; p < 4; ++p) {
        const size_t off0 = (size_t)(2 * p)     * RSTRIDE;
        const size_t off1 = (size_t)(2 * p + 1) * RSTRIDE;
        float v0[VEC], ga0[VEC], be0[VEC];
        float v1[VEC], ga1[VEC], be1[VEC];
        ld_v8_evict_first(xb + off0, v0);      // 2nd read of x: L2 hit, then drop
        ld_v8_evict_first(xb + off1, v1);
        ld_v8_evict_first(gb + off0, ga0);
        ld_v8_evict_first(gb + off1, ga1);
        ld_v8_evict_first(bb + off0, be0);
        ld_v8_evict_first(bb + off1, be1);

        #pragma unroll
        for (int j = 0; j < VEC; ++j) {
            const float2 mi = s_mi[ug * VEC + j];
            v0[j] = fmaf((v0[j] - mi.x) * mi.y, ga0[j], be0[j]);
            v1[j] = fmaf((v1[j] - mi.x) * mi.y, ga1[j], be1[j]);
        }
        st_v4_cs(ob + off0,     v0[0], v0[1], v0[2], v0[3]);
        st_v4_cs(ob + off0 + 4, v0[4], v0[5], v0[6], v0[7]);
        st_v4_cs(ob + off1,     v1[0], v1[1], v1[2], v1[3]);
        st_v4_cs(ob + off1 + 4, v1[4], v1[5], v1[6], v1[7]);
    }
}

extern "C" void kernel_launch(void* const* d_in, const int* in_sizes, int n_in,
                              void* d_out, int out_size) {
    const float* x     = (const float*)d_in[0];
    const float* gamma = (const float*)d_in[1];
    const float* beta  = (const float*)d_in[2];
    float* out = (float*)d_out;

    dim3 grid(UNITS / UB, BATCH);   // (8, 64)
    graphnorm_kernel<<<grid, THREADS>>>(x, gamma, beta, out);
}